// round 12
// baseline (speedup 1.0000x reference)
#include <cuda_runtime.h>
#include <cuda_fp16.h>
#include <math.h>

#define N_RAYS (4*128*128)
#define WARPS_PER_BLOCK 8

// padded packed volume: P2(b, xp, yp, zp) = half2( vpad(x,y,z), vpad(x,y+1,z) )
// xp = x+1 (x in [-1,129]), yp = y+1 (y in [-1,128]), zp = z+4 (z in [-4,131])
#define PZ 136
#define PY 130
#define PX 131
#define SX (PY*PZ)             // 17680
#define PBATCH (PX*SX)         // 2316080
#define ROFF (SX + PZ + 4)     // 17820

__device__ float4   g_ray[N_RAYS * 2];
__device__ unsigned g_P2[4 * PBATCH];      // 37 MB

// ---------------- setup: per-ray geometry ----------------
__global__ void __launch_bounds__(128) drr_setup_kernel(
    const float* __restrict__ params)   // (4,6)
{
    const int ray = blockIdx.x * 128 + threadIdx.x;
    const int iv = ray & 127;
    const int iu = (ray >> 7) & 127;
    const int b  = ray >> 14;

    const float* p = params + b * 6;
    float sx, cx, sy, cy, sz, cz;
    __sincosf(p[0], &sx, &cx);
    __sincosf(p[1], &sy, &cy);
    __sincosf(p[2], &sz, &cz);

    float T00 = cy*cz,  T01 = cx*sz + sx*sy*cz,  T02 = sx*sz - cx*sy*cz;
    float T10 = -cy*sz, T11 = cx*cz - sx*sy*sz,  T12 = sx*cz + cx*sy*sz;
    float T20 = sy,     T21 = -sx*cy,            T22 = cx*cy;

    float tv0 = -p[3], tv1 = -p[4], tv2 = 1000.0f - p[5];
    float s0 = 64.0f - (T00*tv0 + T01*tv1 + T02*tv2);
    float s1 = 64.0f - (T10*tv0 + T11*tv1 + T12*tv2);
    float s2 = 64.0f - (T20*tv0 + T21*tv1 + T22*tv2);

    float qx = ((float)iu + 0.5f) * 0.001f - 0.064f;
    float qy = ((float)iv + 0.5f) * 0.001f - 0.064f;

    float d0 = T00*qx + T01*qy + T02;
    float d1 = T10*qx + T11*qy + T12;
    float d2 = T20*qx + T21*qy + T22;
    float rinv = __fdividef(1.0f, sqrtf(d0*d0 + d1*d1 + d2*d2));
    d0 *= rinv; d1 *= rinv; d2 *= rinv;

    float sd0 = (fabsf(d0) < 1e-8f) ? 1e-8f : d0;
    float sd1 = (fabsf(d1) < 1e-8f) ? 1e-8f : d1;
    float sd2 = (fabsf(d2) < 1e-8f) ? 1e-8f : d2;
    float i0 = __fdividef(1.0f, sd0);
    float i1 = __fdividef(1.0f, sd1);
    float i2 = __fdividef(1.0f, sd2);
    float a0 = (0.0f - s0) * i0, b0_ = (128.0f - s0) * i0;
    float a1 = (0.0f - s1) * i1, b1_ = (128.0f - s1) * i1;
    float a2 = (0.0f - s2) * i2, b2_ = (128.0f - s2) * i2;
    float tmin = fmaxf(fmaxf(fminf(a0,b0_), fminf(a1,b1_)), fminf(a2,b2_));
    tmin = fmaxf(tmin, 0.0f);
    float tmax = fminf(fminf(fmaxf(a0,b0_), fmaxf(a1,b1_)), fmaxf(a2,b2_));

    g_ray[ray*2 + 0] = make_float4(s0, s1, s2, tmin);
    g_ray[ray*2 + 1] = make_float4(d0, d1, d2, tmax);
}

// ---------------- pack: smem row-sharing (each vol row read ONCE) ----------------
// block: fixed (b, x, ygroup of 32); loads rows y0..y0+32 into smem, packs 32 rows
__global__ void __launch_bounds__(256) drr_pack_kernel(
    const float* __restrict__ vol)
{
    __shared__ float srow[33 * 128];          // 16.9 KB

    const int blk = blockIdx.x;               // 4*128*4 = 2048 blocks
    const int yg = blk & 3;
    const int x  = (blk >> 2) & 127;
    const int b  = blk >> 9;
    const int y0 = yg * 32;

    const float* base = vol + (((size_t)(b * 128 + x)) * 128 + y0) * 128;

    // load 33 rows x 32 float4
    for (int i = threadIdx.x; i < 33 * 32; i += 256) {
        const int row = i >> 5;
        const int c4  = i & 31;
        float4 v = make_float4(0.f, 0.f, 0.f, 0.f);
        if (y0 + row < 128)
            v = __ldg((const float4*)(base + row * 128 + c4 * 4));
        *reinterpret_cast<float4*>(&srow[row * 128 + c4 * 4]) = v;
    }
    __syncthreads();

    // pack: thread -> (y_local, z segment of 16)
    const int yl = threadIdx.x >> 3;           // 0..31
    const int z0 = (threadIdx.x & 7) * 16;     // 0..112

    const float* r0 = &srow[yl * 128 + z0];
    const float* r1 = &srow[(yl + 1) * 128 + z0];

    size_t w = (size_t)b * PBATCH + (size_t)(x + 1) * SX
             + (size_t)(y0 + yl + 1) * PZ + (z0 + 4);

    #pragma unroll
    for (int q = 0; q < 4; q++) {
        float4 A = *reinterpret_cast<const float4*>(r0 + q * 4);
        float4 C = *reinterpret_cast<const float4*>(r1 + q * 4);
        __half2 h0 = __floats2half2_rn(A.x, C.x);
        __half2 h1 = __floats2half2_rn(A.y, C.y);
        __half2 h2 = __floats2half2_rn(A.z, C.z);
        __half2 h3 = __floats2half2_rn(A.w, C.w);
        uint4 o;
        o.x = *reinterpret_cast<unsigned*>(&h0);
        o.y = *reinterpret_cast<unsigned*>(&h1);
        o.z = *reinterpret_cast<unsigned*>(&h2);
        o.w = *reinterpret_cast<unsigned*>(&h3);
        *reinterpret_cast<uint4*>(&g_P2[w + q * 4]) = o;
    }
}

// ---------------- borders + y=-1 plane ----------------
#define NB_BORDER (4 * PX * PY)
#define NB_Y0     (4 * 128 * 16)
__global__ void __launch_bounds__(256) drr_border_kernel(
    const float* __restrict__ vol)
{
    const int t = blockIdx.x * 256 + threadIdx.x;
    if (t < NB_BORDER) {
        const int yp = t % PY;
        const int r2 = t / PY;
        const int xp = r2 % PX;
        const int b  = r2 / PX;

        size_t base = (size_t)b * PBATCH + (size_t)xp * SX + (size_t)yp * PZ;
        uint4 z4 = make_uint4(0u, 0u, 0u, 0u);

        if (xp == 0 || xp == 129 || xp == 130 || yp == 129) {
            #pragma unroll
            for (int i = 0; i < PZ / 4; i++)
                *reinterpret_cast<uint4*>(&g_P2[base + i * 4]) = z4;
        } else {
            *reinterpret_cast<uint4*>(&g_P2[base])       = z4;
            *reinterpret_cast<uint4*>(&g_P2[base + 132]) = z4;
        }
        return;
    }
    const int t2 = t - NB_BORDER;
    if (t2 >= NB_Y0) return;
    // yp = 0 plane (y = -1): pair = (0, v(x,0,z))
    const int zb = t2 & 15;
    const int x  = (t2 >> 4) & 127;
    const int b  = t2 >> 11;

    const size_t row = ((size_t)(b * 128 + x)) * 128 * 128;
    const int z0 = zb * 8;

    float4 a0 = __ldg((const float4*)(vol + row + z0));
    float4 a1 = __ldg((const float4*)(vol + row + z0 + 4));

    __half2 h0 = __floats2half2_rn(0.f, a0.x);
    __half2 h1 = __floats2half2_rn(0.f, a0.y);
    __half2 h2 = __floats2half2_rn(0.f, a0.z);
    __half2 h3 = __floats2half2_rn(0.f, a0.w);
    __half2 h4 = __floats2half2_rn(0.f, a1.x);
    __half2 h5 = __floats2half2_rn(0.f, a1.y);
    __half2 h6 = __floats2half2_rn(0.f, a1.z);
    __half2 h7 = __floats2half2_rn(0.f, a1.w);

    uint4 o0, o1;
    o0.x = *reinterpret_cast<unsigned*>(&h0);
    o0.y = *reinterpret_cast<unsigned*>(&h1);
    o0.z = *reinterpret_cast<unsigned*>(&h2);
    o0.w = *reinterpret_cast<unsigned*>(&h3);
    o1.x = *reinterpret_cast<unsigned*>(&h4);
    o1.y = *reinterpret_cast<unsigned*>(&h5);
    o1.z = *reinterpret_cast<unsigned*>(&h6);
    o1.w = *reinterpret_cast<unsigned*>(&h7);

    size_t w = (size_t)b * PBATCH + (size_t)(x + 1) * SX + (z0 + 4);
    *reinterpret_cast<uint4*>(&g_P2[w])     = o0;
    *reinterpret_cast<uint4*>(&g_P2[w + 4]) = o1;
}

// ---------------- march ----------------
__device__ __forceinline__ float drr_lerp(
    const __half2* __restrict__ Ph,
    float px, float py, float pz)
{
    float fx = floorf(px), fy = floorf(py), fz = floorf(pz);
    float rx = px - fx, ry = py - fy, rz = pz - fz;

    int r = (int)fmaf(fx, (float)SX, fmaf(fy, (float)PZ, fz + (float)ROFF));

    __half2 u00 = __ldg(Ph + r);            // (v(y,z),   v(y+1,z))   at x
    __half2 u01 = __ldg(Ph + r + 1);        // z+1 pair (same 128B line)
    __half2 u10 = __ldg(Ph + r + SX);       // x+1
    __half2 u11 = __ldg(Ph + r + SX + 1);

    __half2 rz2 = __float2half2_rn(rz);
    __half2 rx2 = __float2half2_rn(rx);

    // z-lerp and x-lerp in packed fp16 (y-pair rides in vector lanes)
    __half2 L0 = __hfma2(rz2, __hsub2(u01, u00), u00);   // x
    __half2 L1 = __hfma2(rz2, __hsub2(u11, u10), u10);   // x+1
    __half2 M  = __hfma2(rx2, __hsub2(L1, L0), L0);      // x-lerped (y, y+1)

    float2 f = __half22float2(M);
    return fmaf(ry, f.y - f.x, f.x);                     // final y-lerp fp32
}

__device__ __forceinline__ float drr_sample_u(
    const __half2* __restrict__ Ph, float tk,
    float d0, float d1, float d2, float s0, float s1, float s2)
{
    return drr_lerp(Ph, fmaf(tk, d0, s0), fmaf(tk, d1, s1), fmaf(tk, d2, s2));
}

__device__ __forceinline__ float drr_sample_m(
    const __half2* __restrict__ Ph, float tk, float tmax,
    float d0, float d1, float d2, float s0, float s1, float s2)
{
    float tc = fminf(tk, tmax);
    float s = drr_lerp(Ph, fmaf(tc, d0, s0), fmaf(tc, d1, s1), fmaf(tc, d2, s2));
    return (tk < tmax) ? s : 0.0f;
}

__global__ void __launch_bounds__(WARPS_PER_BLOCK * 32, 8) drr_march_kernel(
    float* __restrict__ out)
{
    const int lane    = threadIdx.x & 31;
    const int warp_id = threadIdx.x >> 5;
    const int ray     = blockIdx.x * WARPS_PER_BLOCK + warp_id;
    const int b       = ray >> 14;

    const float4 A = __ldg(&g_ray[ray*2 + 0]);
    const float4 B = __ldg(&g_ray[ray*2 + 1]);
    const float s0 = A.x, s1 = A.y, s2 = A.z, tmin = A.w;
    const float d0 = B.x, d1 = B.y, d2 = B.z, tmax = B.w;

    const __half2* __restrict__ Ph =
        reinterpret_cast<const __half2*>(g_P2) + (size_t)b * PBATCH;

    int nc = __float2int_ru((tmax - tmin - 0.5f) * 0.03125f);
    nc = max(0, min(nc, 8));
    const int nfull = nc - 1;

    const float t0 = tmin + ((float)lane + 0.5f);

    float acc = 0.0f;
    int j = 0;
    for (; j + 1 < nfull; j += 2) {
        float sa = drr_sample_u(Ph, t0 + (float)(j * 32),      d0, d1, d2, s0, s1, s2);
        float sb = drr_sample_u(Ph, t0 + (float)(j * 32 + 32), d0, d1, d2, s0, s1, s2);
        acc += sa + sb;
    }
    if (j < nfull) {
        acc += drr_sample_u(Ph, t0 + (float)(j * 32), d0, d1, d2, s0, s1, s2);
        j++;
    }
    if (j < nc) {
        acc += drr_sample_m(Ph, t0 + (float)(j * 32), tmax, d0, d1, d2, s0, s1, s2);
    }

    #pragma unroll
    for (int off = 16; off > 0; off >>= 1)
        acc += __shfl_xor_sync(0xFFFFFFFFu, acc, off);

    if (lane == 0)
        out[ray] = acc * 0.1f;
}

extern "C" void kernel_launch(void* const* d_in, const int* in_sizes, int n_in,
                              void* d_out, int out_size)
{
    const float* vol    = (const float*)d_in[0];
    const float* params = (const float*)d_in[1];
    float* out = (float*)d_out;

    drr_border_kernel<<<(NB_BORDER + NB_Y0 + 255) / 256, 256>>>(vol);
    drr_pack_kernel<<<4 * 128 * 4, 256>>>(vol);
    drr_setup_kernel<<<N_RAYS / 128, 128>>>(params);
    drr_march_kernel<<<N_RAYS / WARPS_PER_BLOCK, WARPS_PER_BLOCK * 32>>>(out);
}

// round 13
// speedup vs baseline: 1.1820x; 1.1820x over previous
#include <cuda_runtime.h>
#include <cuda_fp16.h>
#include <math.h>

#define N_RAYS (4*128*128)
#define WARPS_PER_BLOCK 8

// padded packed volume: P2(b, xp, yp, zp) = half2( vpad(x,y,z), vpad(x,y+1,z) )
// xp = x+1 (x in [-1,129]), yp = y+1 (y in [-1,128]), zp = z+4 (z in [-4,131])
#define PZ 136
#define PY 130
#define PX 131
#define SX (PY*PZ)             // 17680
#define PBATCH (PX*SX)         // 2316080
#define ROFF (SX + PZ + 4)     // 17820

__device__ float4   g_ray[N_RAYS * 2];
__device__ unsigned g_P2[4 * PBATCH];      // 37 MB

// block-role partition of the fused prep kernel
#define NBLK_PACK   4096                               // 4*128*128*16 threads / 256
#define NB_BORDER   (4 * PX * PY)                      // 68120
#define NB_Y0       (4 * 128 * 16)                     // 8192
#define NBLK_BORDER ((NB_BORDER + NB_Y0 + 255) / 256)  // 299
#define NBLK_SETUP  (N_RAYS / 256)                     // 256
#define NBLK_PREP   (NBLK_PACK + NBLK_BORDER + NBLK_SETUP)

// ---------------- fused prep: pack + border/y0 + setup in one launch ----------------
__global__ void __launch_bounds__(256) drr_prep_kernel(
    const float* __restrict__ vol,
    const float* __restrict__ params)
{
    const int blk = blockIdx.x;

    if (blk < NBLK_PACK) {
        // ---- pack: interior rows (yp in [1,128]) ----
        const int tid = blk * 256 + threadIdx.x;   // 4*128*128*16
        const int zb = tid & 15;
        const int y  = (tid >> 4) & 127;
        const int x  = (tid >> 11) & 127;
        const int b  = tid >> 18;

        const size_t row = (((size_t)(b * 128 + x)) * 128 + y) * 128;
        const int z0 = zb * 8;

        float4 a0 = __ldg((const float4*)(vol + row + z0));
        float4 a1 = __ldg((const float4*)(vol + row + z0 + 4));
        float4 c0 = make_float4(0.f,0.f,0.f,0.f), c1 = c0;
        if (y < 127) {
            c0 = __ldg((const float4*)(vol + row + 128 + z0));
            c1 = __ldg((const float4*)(vol + row + 128 + z0 + 4));
        }

        __half2 h0 = __floats2half2_rn(a0.x, c0.x);
        __half2 h1 = __floats2half2_rn(a0.y, c0.y);
        __half2 h2 = __floats2half2_rn(a0.z, c0.z);
        __half2 h3 = __floats2half2_rn(a0.w, c0.w);
        __half2 h4 = __floats2half2_rn(a1.x, c1.x);
        __half2 h5 = __floats2half2_rn(a1.y, c1.y);
        __half2 h6 = __floats2half2_rn(a1.z, c1.z);
        __half2 h7 = __floats2half2_rn(a1.w, c1.w);

        uint4 o0, o1;
        o0.x = *reinterpret_cast<unsigned*>(&h0);
        o0.y = *reinterpret_cast<unsigned*>(&h1);
        o0.z = *reinterpret_cast<unsigned*>(&h2);
        o0.w = *reinterpret_cast<unsigned*>(&h3);
        o1.x = *reinterpret_cast<unsigned*>(&h4);
        o1.y = *reinterpret_cast<unsigned*>(&h5);
        o1.z = *reinterpret_cast<unsigned*>(&h6);
        o1.w = *reinterpret_cast<unsigned*>(&h7);

        size_t w = (size_t)b * PBATCH + (size_t)(x + 1) * SX + (size_t)(y + 1) * PZ + (z0 + 4);
        *reinterpret_cast<uint4*>(&g_P2[w])     = o0;
        *reinterpret_cast<uint4*>(&g_P2[w + 4]) = o1;
        return;
    }

    if (blk < NBLK_PACK + NBLK_BORDER) {
        // ---- borders + y=-1 plane ----
        const int t = (blk - NBLK_PACK) * 256 + threadIdx.x;
        if (t < NB_BORDER) {
            const int yp = t % PY;
            const int r2 = t / PY;
            const int xp = r2 % PX;
            const int b  = r2 / PX;

            size_t base = (size_t)b * PBATCH + (size_t)xp * SX + (size_t)yp * PZ;
            uint4 z4 = make_uint4(0u, 0u, 0u, 0u);

            if (xp == 0 || xp == 129 || xp == 130 || yp == 129) {
                #pragma unroll
                for (int i = 0; i < PZ / 4; i++)
                    *reinterpret_cast<uint4*>(&g_P2[base + i * 4]) = z4;
            } else {
                *reinterpret_cast<uint4*>(&g_P2[base])       = z4;   // z pads -4..-1
                *reinterpret_cast<uint4*>(&g_P2[base + 132]) = z4;   // z pads 128..131
            }
            return;
        }
        const int t2 = t - NB_BORDER;
        if (t2 >= NB_Y0) return;
        // yp = 0 plane (y = -1): pair = (0, v(x,0,z))
        const int zb = t2 & 15;
        const int x  = (t2 >> 4) & 127;
        const int b  = t2 >> 11;

        const size_t row = ((size_t)(b * 128 + x)) * 128 * 128;   // y = 0 row
        const int z0 = zb * 8;

        float4 a0 = __ldg((const float4*)(vol + row + z0));
        float4 a1 = __ldg((const float4*)(vol + row + z0 + 4));

        __half2 h0 = __floats2half2_rn(0.f, a0.x);
        __half2 h1 = __floats2half2_rn(0.f, a0.y);
        __half2 h2 = __floats2half2_rn(0.f, a0.z);
        __half2 h3 = __floats2half2_rn(0.f, a0.w);
        __half2 h4 = __floats2half2_rn(0.f, a1.x);
        __half2 h5 = __floats2half2_rn(0.f, a1.y);
        __half2 h6 = __floats2half2_rn(0.f, a1.z);
        __half2 h7 = __floats2half2_rn(0.f, a1.w);

        uint4 o0, o1;
        o0.x = *reinterpret_cast<unsigned*>(&h0);
        o0.y = *reinterpret_cast<unsigned*>(&h1);
        o0.z = *reinterpret_cast<unsigned*>(&h2);
        o0.w = *reinterpret_cast<unsigned*>(&h3);
        o1.x = *reinterpret_cast<unsigned*>(&h4);
        o1.y = *reinterpret_cast<unsigned*>(&h5);
        o1.z = *reinterpret_cast<unsigned*>(&h6);
        o1.w = *reinterpret_cast<unsigned*>(&h7);

        size_t w = (size_t)b * PBATCH + (size_t)(x + 1) * SX + (z0 + 4);
        *reinterpret_cast<uint4*>(&g_P2[w])     = o0;
        *reinterpret_cast<uint4*>(&g_P2[w + 4]) = o1;
        return;
    }

    // ---- setup: per-ray geometry ----
    {
        const int ray = (blk - NBLK_PACK - NBLK_BORDER) * 256 + threadIdx.x;
        const int iv = ray & 127;
        const int iu = (ray >> 7) & 127;
        const int b  = ray >> 14;

        const float* p = params + b * 6;
        float sx, cx, sy, cy, szn, czn;
        __sincosf(p[0], &sx, &cx);
        __sincosf(p[1], &sy, &cy);
        __sincosf(p[2], &szn, &czn);

        float T00 = cy*czn,  T01 = cx*szn + sx*sy*czn,  T02 = sx*szn - cx*sy*czn;
        float T10 = -cy*szn, T11 = cx*czn - sx*sy*szn,  T12 = sx*czn + cx*sy*szn;
        float T20 = sy,      T21 = -sx*cy,              T22 = cx*cy;

        float tv0 = -p[3], tv1 = -p[4], tv2 = 1000.0f - p[5];
        float s0 = 64.0f - (T00*tv0 + T01*tv1 + T02*tv2);
        float s1 = 64.0f - (T10*tv0 + T11*tv1 + T12*tv2);
        float s2 = 64.0f - (T20*tv0 + T21*tv1 + T22*tv2);

        float qx = ((float)iu + 0.5f) * 0.001f - 0.064f;
        float qy = ((float)iv + 0.5f) * 0.001f - 0.064f;

        float d0 = T00*qx + T01*qy + T02;
        float d1 = T10*qx + T11*qy + T12;
        float d2 = T20*qx + T21*qy + T22;
        float rinv = __fdividef(1.0f, sqrtf(d0*d0 + d1*d1 + d2*d2));
        d0 *= rinv; d1 *= rinv; d2 *= rinv;

        float sd0 = (fabsf(d0) < 1e-8f) ? 1e-8f : d0;
        float sd1 = (fabsf(d1) < 1e-8f) ? 1e-8f : d1;
        float sd2 = (fabsf(d2) < 1e-8f) ? 1e-8f : d2;
        float i0 = __fdividef(1.0f, sd0);
        float i1 = __fdividef(1.0f, sd1);
        float i2 = __fdividef(1.0f, sd2);
        float a0 = (0.0f - s0) * i0, b0_ = (128.0f - s0) * i0;
        float a1 = (0.0f - s1) * i1, b1_ = (128.0f - s1) * i1;
        float a2 = (0.0f - s2) * i2, b2_ = (128.0f - s2) * i2;
        float tmin = fmaxf(fmaxf(fminf(a0,b0_), fminf(a1,b1_)), fminf(a2,b2_));
        tmin = fmaxf(tmin, 0.0f);
        float tmax = fminf(fminf(fmaxf(a0,b0_), fmaxf(a1,b1_)), fmaxf(a2,b2_));

        g_ray[ray*2 + 0] = make_float4(s0, s1, s2, tmin);
        g_ray[ray*2 + 1] = make_float4(d0, d1, d2, tmax);
    }
}

// ---------------- march (round-11 proven body) ----------------
__device__ __forceinline__ float drr_lerp(
    const unsigned* __restrict__ P,
    float px, float py, float pz)
{
    float fx = floorf(px), fy = floorf(py), fz = floorf(pz);
    float rx = px - fx, ry = py - fy, rz = pz - fz;

    int r = (int)fmaf(fx, (float)SX, fmaf(fy, (float)PZ, fz + (float)ROFF));

    unsigned u00 = __ldg(P + r);            // (x  ): (v(y,z), v(y+1,z))
    unsigned u01 = __ldg(P + r + 1);        // z+1 pair (same 128B line)
    unsigned u10 = __ldg(P + r + SX);       // (x+1)
    unsigned u11 = __ldg(P + r + SX + 1);

    float2 f00 = __half22float2(*reinterpret_cast<__half2*>(&u00));
    float2 f01 = __half22float2(*reinterpret_cast<__half2*>(&u01));
    float2 f10 = __half22float2(*reinterpret_cast<__half2*>(&u10));
    float2 f11 = __half22float2(*reinterpret_cast<__half2*>(&u11));

    float z0a = fmaf(rz, f01.x - f00.x, f00.x);
    float z0b = fmaf(rz, f01.y - f00.y, f00.y);
    float z1a = fmaf(rz, f11.x - f10.x, f10.x);
    float z1b = fmaf(rz, f11.y - f10.y, f10.y);
    float ly0 = fmaf(ry, z0b - z0a, z0a);
    float ly1 = fmaf(ry, z1b - z1a, z1a);
    return fmaf(rx, ly1 - ly0, ly0);
}

__device__ __forceinline__ float drr_sample_u(
    const unsigned* __restrict__ P, float tk,
    float d0, float d1, float d2, float s0, float s1, float s2)
{
    return drr_lerp(P, fmaf(tk, d0, s0), fmaf(tk, d1, s1), fmaf(tk, d2, s2));
}

__device__ __forceinline__ float drr_sample_m(
    const unsigned* __restrict__ P, float tk, float tmax,
    float d0, float d1, float d2, float s0, float s1, float s2)
{
    float tc = fminf(tk, tmax);
    float s = drr_lerp(P, fmaf(tc, d0, s0), fmaf(tc, d1, s1), fmaf(tc, d2, s2));
    return (tk < tmax) ? s : 0.0f;
}

__global__ void __launch_bounds__(WARPS_PER_BLOCK * 32, 8) drr_march_kernel(
    float* __restrict__ out)
{
    const int lane    = threadIdx.x & 31;
    const int warp_id = threadIdx.x >> 5;
    const int ray     = blockIdx.x * WARPS_PER_BLOCK + warp_id;
    const int b       = ray >> 14;

    const float4 A = __ldg(&g_ray[ray*2 + 0]);
    const float4 B = __ldg(&g_ray[ray*2 + 1]);
    const float s0 = A.x, s1 = A.y, s2 = A.z, tmin = A.w;
    const float d0 = B.x, d1 = B.y, d2 = B.z, tmax = B.w;

    const unsigned* __restrict__ P = g_P2 + (size_t)b * PBATCH;

    int nc = __float2int_ru((tmax - tmin - 0.5f) * 0.03125f);
    nc = max(0, min(nc, 8));
    const int nfull = nc - 1;

    const float t0 = tmin + ((float)lane + 0.5f);

    float acc = 0.0f;
    int j = 0;
    for (; j + 1 < nfull; j += 2) {
        float sa = drr_sample_u(P, t0 + (float)(j * 32),      d0, d1, d2, s0, s1, s2);
        float sb = drr_sample_u(P, t0 + (float)(j * 32 + 32), d0, d1, d2, s0, s1, s2);
        acc += sa + sb;
    }
    if (j < nfull) {
        acc += drr_sample_u(P, t0 + (float)(j * 32), d0, d1, d2, s0, s1, s2);
        j++;
    }
    if (j < nc) {
        acc += drr_sample_m(P, t0 + (float)(j * 32), tmax, d0, d1, d2, s0, s1, s2);
    }

    #pragma unroll
    for (int off = 16; off > 0; off >>= 1)
        acc += __shfl_xor_sync(0xFFFFFFFFu, acc, off);

    if (lane == 0)
        out[ray] = acc * 0.1f;
}

extern "C" void kernel_launch(void* const* d_in, const int* in_sizes, int n_in,
                              void* d_out, int out_size)
{
    const float* vol    = (const float*)d_in[0];
    const float* params = (const float*)d_in[1];
    float* out = (float*)d_out;

    drr_prep_kernel<<<NBLK_PREP, 256>>>(vol, params);
    drr_march_kernel<<<N_RAYS / WARPS_PER_BLOCK, WARPS_PER_BLOCK * 32>>>(out);
}

// round 14
// speedup vs baseline: 1.2410x; 1.0499x over previous
#include <cuda_runtime.h>
#include <cuda_fp16.h>
#include <math.h>

#define N_RAYS (4*128*128)
#define WARPS_PER_BLOCK 8

// padded packed volume: P2(b, xp, yp, zp) = half2( vpad(x,y,z), vpad(x,y+1,z) )
// xp = x+1 (x in [-1,129]), yp = y+1 (y in [-1,128]), zp = z+4 (z in [-4,131])
#define PZ 136
#define PY 130
#define PX 131
#define SX (PY*PZ)             // 17680
#define PBATCH (PX*SX)         // 2316080
#define ROFF (SX + PZ + 4)     // 17820

__device__ float4   g_ray[N_RAYS * 2];
__device__ unsigned g_P2[4 * PBATCH];      // 37 MB

// block-role partition of the fused prep kernel
// pack: thread = (b, x, ygroup of 16, zseg of 4) -> 4*128*8*32 = 131072 threads
#define NBLK_PACK   512
#define NB_BORDER   (4 * PX * PY)                      // 68120
#define NB_Y0       (4 * 128 * 16)                     // 8192
#define NBLK_BORDER ((NB_BORDER + NB_Y0 + 255) / 256)  // 299
#define NBLK_SETUP  (N_RAYS / 256)                     // 256
#define NBLK_PREP   (NBLK_PACK + NBLK_BORDER + NBLK_SETUP)

// ---------------- fused prep: pack + border/y0 + setup in one launch ----------------
__global__ void __launch_bounds__(256) drr_prep_kernel(
    const float* __restrict__ vol,
    const float* __restrict__ params)
{
    const int blk = blockIdx.x;

    if (blk < NBLK_PACK) {
        // ---- pack: rolling-register, each vol row read ONCE ----
        const int tid = blk * 256 + threadIdx.x;   // 131072
        const int zq = tid & 31;                   // z segment (4 floats)
        const int yg = (tid >> 5) & 7;             // y group of 16
        const int x  = (tid >> 8) & 127;
        const int b  = tid >> 15;
        const int y0 = yg * 16;

        const float* src = vol + ((size_t)(b * 128 + x) * 128 + y0) * 128 + zq * 4;
        size_t w = (size_t)b * PBATCH + (size_t)(x + 1) * SX
                 + (size_t)(y0 + 1) * PZ + (zq * 4 + 4);

        float4 prev = __ldg((const float4*)src);
        #pragma unroll
        for (int i = 1; i <= 16; i++) {
            float4 cur = make_float4(0.f, 0.f, 0.f, 0.f);
            if (y0 + i < 128)                       // warp-uniform (yg uniform in warp)
                cur = __ldg((const float4*)(src + (size_t)i * 128));

            __half2 h0 = __floats2half2_rn(prev.x, cur.x);
            __half2 h1 = __floats2half2_rn(prev.y, cur.y);
            __half2 h2 = __floats2half2_rn(prev.z, cur.z);
            __half2 h3 = __floats2half2_rn(prev.w, cur.w);
            uint4 o;
            o.x = *reinterpret_cast<unsigned*>(&h0);
            o.y = *reinterpret_cast<unsigned*>(&h1);
            o.z = *reinterpret_cast<unsigned*>(&h2);
            o.w = *reinterpret_cast<unsigned*>(&h3);
            *reinterpret_cast<uint4*>(&g_P2[w + (size_t)(i - 1) * PZ]) = o;

            prev = cur;
        }
        return;
    }

    if (blk < NBLK_PACK + NBLK_BORDER) {
        // ---- borders + y=-1 plane ----
        const int t = (blk - NBLK_PACK) * 256 + threadIdx.x;
        if (t < NB_BORDER) {
            const int yp = t % PY;
            const int r2 = t / PY;
            const int xp = r2 % PX;
            const int b  = r2 / PX;

            size_t base = (size_t)b * PBATCH + (size_t)xp * SX + (size_t)yp * PZ;
            uint4 z4 = make_uint4(0u, 0u, 0u, 0u);

            if (xp == 0 || xp == 129 || xp == 130 || yp == 129) {
                #pragma unroll
                for (int i = 0; i < PZ / 4; i++)
                    *reinterpret_cast<uint4*>(&g_P2[base + i * 4]) = z4;
            } else {
                *reinterpret_cast<uint4*>(&g_P2[base])       = z4;   // z pads -4..-1
                *reinterpret_cast<uint4*>(&g_P2[base + 132]) = z4;   // z pads 128..131
            }
            return;
        }
        const int t2 = t - NB_BORDER;
        if (t2 >= NB_Y0) return;
        // yp = 0 plane (y = -1): pair = (0, v(x,0,z))
        const int zb = t2 & 15;
        const int x  = (t2 >> 4) & 127;
        const int b  = t2 >> 11;

        const size_t row = ((size_t)(b * 128 + x)) * 128 * 128;   // y = 0 row
        const int z0 = zb * 8;

        float4 a0 = __ldg((const float4*)(vol + row + z0));
        float4 a1 = __ldg((const float4*)(vol + row + z0 + 4));

        __half2 h0 = __floats2half2_rn(0.f, a0.x);
        __half2 h1 = __floats2half2_rn(0.f, a0.y);
        __half2 h2 = __floats2half2_rn(0.f, a0.z);
        __half2 h3 = __floats2half2_rn(0.f, a0.w);
        __half2 h4 = __floats2half2_rn(0.f, a1.x);
        __half2 h5 = __floats2half2_rn(0.f, a1.y);
        __half2 h6 = __floats2half2_rn(0.f, a1.z);
        __half2 h7 = __floats2half2_rn(0.f, a1.w);

        uint4 o0, o1;
        o0.x = *reinterpret_cast<unsigned*>(&h0);
        o0.y = *reinterpret_cast<unsigned*>(&h1);
        o0.z = *reinterpret_cast<unsigned*>(&h2);
        o0.w = *reinterpret_cast<unsigned*>(&h3);
        o1.x = *reinterpret_cast<unsigned*>(&h4);
        o1.y = *reinterpret_cast<unsigned*>(&h5);
        o1.z = *reinterpret_cast<unsigned*>(&h6);
        o1.w = *reinterpret_cast<unsigned*>(&h7);

        size_t w = (size_t)b * PBATCH + (size_t)(x + 1) * SX + (z0 + 4);
        *reinterpret_cast<uint4*>(&g_P2[w])     = o0;
        *reinterpret_cast<uint4*>(&g_P2[w + 4]) = o1;
        return;
    }

    // ---- setup: per-ray geometry ----
    {
        const int ray = (blk - NBLK_PACK - NBLK_BORDER) * 256 + threadIdx.x;
        const int iv = ray & 127;
        const int iu = (ray >> 7) & 127;
        const int b  = ray >> 14;

        const float* p = params + b * 6;
        float sx, cx, sy, cy, szn, czn;
        __sincosf(p[0], &sx, &cx);
        __sincosf(p[1], &sy, &cy);
        __sincosf(p[2], &szn, &czn);

        float T00 = cy*czn,  T01 = cx*szn + sx*sy*czn,  T02 = sx*szn - cx*sy*czn;
        float T10 = -cy*szn, T11 = cx*czn - sx*sy*szn,  T12 = sx*czn + cx*sy*szn;
        float T20 = sy,      T21 = -sx*cy,              T22 = cx*cy;

        float tv0 = -p[3], tv1 = -p[4], tv2 = 1000.0f - p[5];
        float s0 = 64.0f - (T00*tv0 + T01*tv1 + T02*tv2);
        float s1 = 64.0f - (T10*tv0 + T11*tv1 + T12*tv2);
        float s2 = 64.0f - (T20*tv0 + T21*tv1 + T22*tv2);

        float qx = ((float)iu + 0.5f) * 0.001f - 0.064f;
        float qy = ((float)iv + 0.5f) * 0.001f - 0.064f;

        float d0 = T00*qx + T01*qy + T02;
        float d1 = T10*qx + T11*qy + T12;
        float d2 = T20*qx + T21*qy + T22;
        float rinv = __fdividef(1.0f, sqrtf(d0*d0 + d1*d1 + d2*d2));
        d0 *= rinv; d1 *= rinv; d2 *= rinv;

        float sd0 = (fabsf(d0) < 1e-8f) ? 1e-8f : d0;
        float sd1 = (fabsf(d1) < 1e-8f) ? 1e-8f : d1;
        float sd2 = (fabsf(d2) < 1e-8f) ? 1e-8f : d2;
        float i0 = __fdividef(1.0f, sd0);
        float i1 = __fdividef(1.0f, sd1);
        float i2 = __fdividef(1.0f, sd2);
        float a0 = (0.0f - s0) * i0, b0_ = (128.0f - s0) * i0;
        float a1 = (0.0f - s1) * i1, b1_ = (128.0f - s1) * i1;
        float a2 = (0.0f - s2) * i2, b2_ = (128.0f - s2) * i2;
        float tmin = fmaxf(fmaxf(fminf(a0,b0_), fminf(a1,b1_)), fminf(a2,b2_));
        tmin = fmaxf(tmin, 0.0f);
        float tmax = fminf(fminf(fmaxf(a0,b0_), fmaxf(a1,b1_)), fmaxf(a2,b2_));

        g_ray[ray*2 + 0] = make_float4(s0, s1, s2, tmin);
        g_ray[ray*2 + 1] = make_float4(d0, d1, d2, tmax);
    }
}

// ---------------- march (round-11/13 proven body, unchanged) ----------------
__device__ __forceinline__ float drr_lerp(
    const unsigned* __restrict__ P,
    float px, float py, float pz)
{
    float fx = floorf(px), fy = floorf(py), fz = floorf(pz);
    float rx = px - fx, ry = py - fy, rz = pz - fz;

    int r = (int)fmaf(fx, (float)SX, fmaf(fy, (float)PZ, fz + (float)ROFF));

    unsigned u00 = __ldg(P + r);            // (x  ): (v(y,z), v(y+1,z))
    unsigned u01 = __ldg(P + r + 1);        // z+1 pair (same 128B line)
    unsigned u10 = __ldg(P + r + SX);       // (x+1)
    unsigned u11 = __ldg(P + r + SX + 1);

    float2 f00 = __half22float2(*reinterpret_cast<__half2*>(&u00));
    float2 f01 = __half22float2(*reinterpret_cast<__half2*>(&u01));
    float2 f10 = __half22float2(*reinterpret_cast<__half2*>(&u10));
    float2 f11 = __half22float2(*reinterpret_cast<__half2*>(&u11));

    float z0a = fmaf(rz, f01.x - f00.x, f00.x);
    float z0b = fmaf(rz, f01.y - f00.y, f00.y);
    float z1a = fmaf(rz, f11.x - f10.x, f10.x);
    float z1b = fmaf(rz, f11.y - f10.y, f10.y);
    float ly0 = fmaf(ry, z0b - z0a, z0a);
    float ly1 = fmaf(ry, z1b - z1a, z1a);
    return fmaf(rx, ly1 - ly0, ly0);
}

__device__ __forceinline__ float drr_sample_u(
    const unsigned* __restrict__ P, float tk,
    float d0, float d1, float d2, float s0, float s1, float s2)
{
    return drr_lerp(P, fmaf(tk, d0, s0), fmaf(tk, d1, s1), fmaf(tk, d2, s2));
}

__device__ __forceinline__ float drr_sample_m(
    const unsigned* __restrict__ P, float tk, float tmax,
    float d0, float d1, float d2, float s0, float s1, float s2)
{
    float tc = fminf(tk, tmax);
    float s = drr_lerp(P, fmaf(tc, d0, s0), fmaf(tc, d1, s1), fmaf(tc, d2, s2));
    return (tk < tmax) ? s : 0.0f;
}

__global__ void __launch_bounds__(WARPS_PER_BLOCK * 32, 8) drr_march_kernel(
    float* __restrict__ out)
{
    const int lane    = threadIdx.x & 31;
    const int warp_id = threadIdx.x >> 5;
    const int ray     = blockIdx.x * WARPS_PER_BLOCK + warp_id;
    const int b       = ray >> 14;

    const float4 A = __ldg(&g_ray[ray*2 + 0]);
    const float4 B = __ldg(&g_ray[ray*2 + 1]);
    const float s0 = A.x, s1 = A.y, s2 = A.z, tmin = A.w;
    const float d0 = B.x, d1 = B.y, d2 = B.z, tmax = B.w;

    const unsigned* __restrict__ P = g_P2 + (size_t)b * PBATCH;

    int nc = __float2int_ru((tmax - tmin - 0.5f) * 0.03125f);
    nc = max(0, min(nc, 8));
    const int nfull = nc - 1;

    const float t0 = tmin + ((float)lane + 0.5f);

    float acc = 0.0f;
    int j = 0;
    for (; j + 1 < nfull; j += 2) {
        float sa = drr_sample_u(P, t0 + (float)(j * 32),      d0, d1, d2, s0, s1, s2);
        float sb = drr_sample_u(P, t0 + (float)(j * 32 + 32), d0, d1, d2, s0, s1, s2);
        acc += sa + sb;
    }
    if (j < nfull) {
        acc += drr_sample_u(P, t0 + (float)(j * 32), d0, d1, d2, s0, s1, s2);
        j++;
    }
    if (j < nc) {
        acc += drr_sample_m(P, t0 + (float)(j * 32), tmax, d0, d1, d2, s0, s1, s2);
    }

    #pragma unroll
    for (int off = 16; off > 0; off >>= 1)
        acc += __shfl_xor_sync(0xFFFFFFFFu, acc, off);

    if (lane == 0)
        out[ray] = acc * 0.1f;
}

extern "C" void kernel_launch(void* const* d_in, const int* in_sizes, int n_in,
                              void* d_out, int out_size)
{
    const float* vol    = (const float*)d_in[0];
    const float* params = (const float*)d_in[1];
    float* out = (float*)d_out;

    drr_prep_kernel<<<NBLK_PREP, 256>>>(vol, params);
    drr_march_kernel<<<N_RAYS / WARPS_PER_BLOCK, WARPS_PER_BLOCK * 32>>>(out);
}

// round 15
// speedup vs baseline: 1.3040x; 1.0508x over previous
#include <cuda_runtime.h>
#include <math.h>

#define N_RAYS (4*128*128)
#define WARPS_PER_BLOCK 8

// padded quantized y-pair volume: P2(b, xp, yp, zp) = uchar2( q(x,y,z), q(x,y+1,z) )
// q = round(255*v); xp=x+1 (x in [-1,129]), yp=y+1 (y in [-1,128]), zp=z+4 (z in [-4,131])
#define PZ 136
#define PY 130
#define PX 131
#define SX (PY*PZ)             // 17680
#define PBATCH (PX*SX)         // 2316080
#define ROFF (SX + PZ + 4)     // 17820

__device__ float4         g_ray[N_RAYS * 2];
__device__ unsigned short g_P2[4 * PBATCH];      // 18.5 MB

// block-role partition of the fused prep kernel
#define NBLK_PACK   512                                // 4*128*8*32 threads / 256
#define NB_BORDER   (4 * PX * PY)                      // 68120
#define NB_Y0       (4 * 128 * 16)                     // 8192
#define NBLK_BORDER ((NB_BORDER + NB_Y0 + 255) / 256)  // 299
#define NBLK_SETUP  (N_RAYS / 256)                     // 256
#define NBLK_PREP   (NBLK_PACK + NBLK_BORDER + NBLK_SETUP)

__device__ __forceinline__ unsigned q8(float v) {
    return __float2uint_rn(v * 255.0f);
}

// ---------------- fused prep: pack + border/y0 + setup in one launch ----------------
__global__ void __launch_bounds__(256) drr_prep_kernel(
    const float* __restrict__ vol,
    const float* __restrict__ params)
{
    const int blk = blockIdx.x;

    if (blk < NBLK_PACK) {
        // ---- pack: rolling-register, each vol row read ONCE, quantize to u8 ----
        const int tid = blk * 256 + threadIdx.x;   // 131072
        const int zq = tid & 31;                   // z segment (4 floats)
        const int yg = (tid >> 5) & 7;             // y group of 16
        const int x  = (tid >> 8) & 127;
        const int b  = tid >> 15;
        const int y0 = yg * 16;

        const float* src = vol + ((size_t)(b * 128 + x) * 128 + y0) * 128 + zq * 4;
        size_t w = (size_t)b * PBATCH + (size_t)(x + 1) * SX
                 + (size_t)(y0 + 1) * PZ + (zq * 4 + 4);

        float4 prev = __ldg((const float4*)src);
        #pragma unroll
        for (int i = 1; i <= 16; i++) {
            float4 cur = make_float4(0.f, 0.f, 0.f, 0.f);
            if (y0 + i < 128)                       // warp-uniform (yg uniform in warp)
                cur = __ldg((const float4*)(src + (size_t)i * 128));

            unsigned u0 =  q8(prev.x)       | (q8(cur.x) << 8)
                        | (q8(prev.y) << 16)| (q8(cur.y) << 24);
            unsigned u1 =  q8(prev.z)       | (q8(cur.z) << 8)
                        | (q8(prev.w) << 16)| (q8(cur.w) << 24);

            *reinterpret_cast<uint2*>(&g_P2[w + (size_t)(i - 1) * PZ]) = make_uint2(u0, u1);
            prev = cur;
        }
        return;
    }

    if (blk < NBLK_PACK + NBLK_BORDER) {
        // ---- borders + y=-1 plane ----
        const int t = (blk - NBLK_PACK) * 256 + threadIdx.x;
        if (t < NB_BORDER) {
            const int yp = t % PY;
            const int r2 = t / PY;
            const int xp = r2 % PX;
            const int b  = r2 / PX;

            size_t base = (size_t)b * PBATCH + (size_t)xp * SX + (size_t)yp * PZ;

            if (xp == 0 || xp == 129 || xp == 130 || yp == 129) {
                // full zero row: 136 ushorts = 272 B = 17 x 16 B (base is 16B-aligned)
                uint4 z4 = make_uint4(0u, 0u, 0u, 0u);
                #pragma unroll
                for (int i = 0; i < 17; i++)
                    *reinterpret_cast<uint4*>(&g_P2[base + i * 8]) = z4;
            } else {
                uint2 z2 = make_uint2(0u, 0u);
                *reinterpret_cast<uint2*>(&g_P2[base])       = z2;   // z pads -4..-1
                *reinterpret_cast<uint2*>(&g_P2[base + 132]) = z2;   // z pads 128..131
            }
            return;
        }
        const int t2 = t - NB_BORDER;
        if (t2 >= NB_Y0) return;
        // yp = 0 plane (y = -1): pair = (0, q(x,0,z)) -> q in high byte
        const int zb = t2 & 15;
        const int x  = (t2 >> 4) & 127;
        const int b  = t2 >> 11;

        const size_t row = ((size_t)(b * 128 + x)) * 128 * 128;   // y = 0 row
        const int z0 = zb * 8;

        float4 a0 = __ldg((const float4*)(vol + row + z0));
        float4 a1 = __ldg((const float4*)(vol + row + z0 + 4));

        unsigned u0 = (q8(a0.x) << 8) | (q8(a0.y) << 24);
        unsigned u1 = (q8(a0.z) << 8) | (q8(a0.w) << 24);
        unsigned u2 = (q8(a1.x) << 8) | (q8(a1.y) << 24);
        unsigned u3 = (q8(a1.z) << 8) | (q8(a1.w) << 24);

        size_t w = (size_t)b * PBATCH + (size_t)(x + 1) * SX + (z0 + 4);
        *reinterpret_cast<uint2*>(&g_P2[w])     = make_uint2(u0, u1);
        *reinterpret_cast<uint2*>(&g_P2[w + 4]) = make_uint2(u2, u3);
        return;
    }

    // ---- setup: per-ray geometry ----
    {
        const int ray = (blk - NBLK_PACK - NBLK_BORDER) * 256 + threadIdx.x;
        const int iv = ray & 127;
        const int iu = (ray >> 7) & 127;
        const int b  = ray >> 14;

        const float* p = params + b * 6;
        float sx, cx, sy, cy, szn, czn;
        __sincosf(p[0], &sx, &cx);
        __sincosf(p[1], &sy, &cy);
        __sincosf(p[2], &szn, &czn);

        float T00 = cy*czn,  T01 = cx*szn + sx*sy*czn,  T02 = sx*szn - cx*sy*czn;
        float T10 = -cy*szn, T11 = cx*czn - sx*sy*szn,  T12 = sx*czn + cx*sy*szn;
        float T20 = sy,      T21 = -sx*cy,              T22 = cx*cy;

        float tv0 = -p[3], tv1 = -p[4], tv2 = 1000.0f - p[5];
        float s0 = 64.0f - (T00*tv0 + T01*tv1 + T02*tv2);
        float s1 = 64.0f - (T10*tv0 + T11*tv1 + T12*tv2);
        float s2 = 64.0f - (T20*tv0 + T21*tv1 + T22*tv2);

        float qx = ((float)iu + 0.5f) * 0.001f - 0.064f;
        float qy = ((float)iv + 0.5f) * 0.001f - 0.064f;

        float d0 = T00*qx + T01*qy + T02;
        float d1 = T10*qx + T11*qy + T12;
        float d2 = T20*qx + T21*qy + T22;
        float rinv = __fdividef(1.0f, sqrtf(d0*d0 + d1*d1 + d2*d2));
        d0 *= rinv; d1 *= rinv; d2 *= rinv;

        float sd0 = (fabsf(d0) < 1e-8f) ? 1e-8f : d0;
        float sd1 = (fabsf(d1) < 1e-8f) ? 1e-8f : d1;
        float sd2 = (fabsf(d2) < 1e-8f) ? 1e-8f : d2;
        float i0 = __fdividef(1.0f, sd0);
        float i1 = __fdividef(1.0f, sd1);
        float i2 = __fdividef(1.0f, sd2);
        float a0 = (0.0f - s0) * i0, b0_ = (128.0f - s0) * i0;
        float a1 = (0.0f - s1) * i1, b1_ = (128.0f - s1) * i1;
        float a2 = (0.0f - s2) * i2, b2_ = (128.0f - s2) * i2;
        float tmin = fmaxf(fmaxf(fminf(a0,b0_), fminf(a1,b1_)), fminf(a2,b2_));
        tmin = fmaxf(tmin, 0.0f);
        float tmax = fminf(fminf(fmaxf(a0,b0_), fmaxf(a1,b1_)), fmaxf(a2,b2_));

        g_ray[ray*2 + 0] = make_float4(s0, s1, s2, tmin);
        g_ray[ray*2 + 1] = make_float4(d0, d1, d2, tmax);
    }
}

// ---------------- march ----------------
#define QMAGIC 0x4B000000u      // 2^23: float with q in low mantissa bits
#define QC     8388608.0f

__device__ __forceinline__ float drr_lerp(
    const unsigned short* __restrict__ P,
    float px, float py, float pz)
{
    float fx = floorf(px), fy = floorf(py), fz = floorf(pz);
    float rx = px - fx, ry = py - fy, rz = pz - fz;

    int r = (int)fmaf(fx, (float)SX, fmaf(fy, (float)PZ, fz + (float)ROFF));

    unsigned u00 = __ldg(P + r);            // (q(y,z), q(y+1,z)) at x
    unsigned u01 = __ldg(P + r + 1);        // z+1 pair (same 128B line)
    unsigned u10 = __ldg(P + r + SX);       // x+1
    unsigned u11 = __ldg(P + r + SX + 1);

    // magic unpack: float = 2^23 + q
    float f00a = __uint_as_float(__byte_perm(u00, QMAGIC, 0x7440));
    float f00b = __uint_as_float(__byte_perm(u00, QMAGIC, 0x7441));
    float f01a = __uint_as_float(__byte_perm(u01, QMAGIC, 0x7440));
    float f01b = __uint_as_float(__byte_perm(u01, QMAGIC, 0x7441));
    float f10a = __uint_as_float(__byte_perm(u10, QMAGIC, 0x7440));
    float f10b = __uint_as_float(__byte_perm(u10, QMAGIC, 0x7441));
    float f11a = __uint_as_float(__byte_perm(u11, QMAGIC, 0x7440));
    float f11b = __uint_as_float(__byte_perm(u11, QMAGIC, 0x7441));

    // z-lerp with exact offset removal (f - QC and diffs are exact small ints)
    float z0a = fmaf(rz, f01a - f00a, f00a - QC);
    float z0b = fmaf(rz, f01b - f00b, f00b - QC);
    float z1a = fmaf(rz, f11a - f10a, f10a - QC);
    float z1b = fmaf(rz, f11b - f10b, f10b - QC);
    float ly0 = fmaf(ry, z0b - z0a, z0a);
    float ly1 = fmaf(ry, z1b - z1a, z1a);
    return fmaf(rx, ly1 - ly0, ly0);
}

__device__ __forceinline__ float drr_sample_u(
    const unsigned short* __restrict__ P, float tk,
    float d0, float d1, float d2, float s0, float s1, float s2)
{
    return drr_lerp(P, fmaf(tk, d0, s0), fmaf(tk, d1, s1), fmaf(tk, d2, s2));
}

__device__ __forceinline__ float drr_sample_m(
    const unsigned short* __restrict__ P, float tk, float tmax,
    float d0, float d1, float d2, float s0, float s1, float s2)
{
    float tc = fminf(tk, tmax);
    float s = drr_lerp(P, fmaf(tc, d0, s0), fmaf(tc, d1, s1), fmaf(tc, d2, s2));
    return (tk < tmax) ? s : 0.0f;
}

__global__ void __launch_bounds__(WARPS_PER_BLOCK * 32, 8) drr_march_kernel(
    float* __restrict__ out)
{
    const int lane    = threadIdx.x & 31;
    const int warp_id = threadIdx.x >> 5;
    const int ray     = blockIdx.x * WARPS_PER_BLOCK + warp_id;
    const int b       = ray >> 14;

    const float4 A = __ldg(&g_ray[ray*2 + 0]);
    const float4 B = __ldg(&g_ray[ray*2 + 1]);
    const float s0 = A.x, s1 = A.y, s2 = A.z, tmin = A.w;
    const float d0 = B.x, d1 = B.y, d2 = B.z, tmax = B.w;

    const unsigned short* __restrict__ P = g_P2 + (size_t)b * PBATCH;

    int nc = __float2int_ru((tmax - tmin - 0.5f) * 0.03125f);
    nc = max(0, min(nc, 8));
    const int nfull = nc - 1;

    const float t0 = tmin + ((float)lane + 0.5f);

    float acc = 0.0f;
    int j = 0;
    for (; j + 1 < nfull; j += 2) {
        float sa = drr_sample_u(P, t0 + (float)(j * 32),      d0, d1, d2, s0, s1, s2);
        float sb = drr_sample_u(P, t0 + (float)(j * 32 + 32), d0, d1, d2, s0, s1, s2);
        acc += sa + sb;
    }
    if (j < nfull) {
        acc += drr_sample_u(P, t0 + (float)(j * 32), d0, d1, d2, s0, s1, s2);
        j++;
    }
    if (j < nc) {
        acc += drr_sample_m(P, t0 + (float)(j * 32), tmax, d0, d1, d2, s0, s1, s2);
    }

    #pragma unroll
    for (int off = 16; off > 0; off >>= 1)
        acc += __shfl_xor_sync(0xFFFFFFFFu, acc, off);

    if (lane == 0)
        out[ray] = acc * (0.1f / 255.0f);
}

extern "C" void kernel_launch(void* const* d_in, const int* in_sizes, int n_in,
                              void* d_out, int out_size)
{
    const float* vol    = (const float*)d_in[0];
    const float* params = (const float*)d_in[1];
    float* out = (float*)d_out;

    drr_prep_kernel<<<NBLK_PREP, 256>>>(vol, params);
    drr_march_kernel<<<N_RAYS / WARPS_PER_BLOCK, WARPS_PER_BLOCK * 32>>>(out);
}